// round 8
// baseline (speedup 1.0000x reference)
#include <cuda_runtime.h>
#include <cuda_bf16.h>

#define NMAX 50000
#define EMAX 1700000

// ---------------- scratch ----------------
__device__ __nv_bfloat162 g_h1b[NMAX * 32];   // x@W1 in bf16 (only consumer: agg1)
__device__ float g_asrc1[NMAX * 8];
__device__ float g_adst1[NMAX * 8];
__device__ float g_h2in[NMAX * 64];
__device__ float g_h2[NMAX * 40];
__device__ float g_as2[NMAX];
__device__ float g_ad2[NMAX];
// CSR
__device__ int g_deg[NMAX];
__device__ int g_start[NMAX + 1];
__device__ int g_cursor[NMAX];
__device__ int g_csrc[EMAX];
__device__ int g_bsum[64];

__device__ __forceinline__ float leaky(float e) { return e >= 0.f ? e : 0.2f * e; }

// ---------------- SGEMM1: h1 = A[M,512] @ B[512,64], bf16 store + fused attn logits ----------------
// BM=128 BN=64 BK=16, 128 threads, 8x8 microtile, double-buffered.
__global__ void __launch_bounds__(128) sgemm1k(const float* __restrict__ A,
                                               const float* __restrict__ B,
                                               const float* __restrict__ att_src,
                                               const float* __restrict__ att_dst,
                                               int M) {
    const int K = 512, N = 64;
    __shared__ float As[2][16][128];
    __shared__ float Bs[2][16][64];
    int tid = threadIdx.x;
    int tx = tid & 7, ty = tid >> 3;
    int row0 = blockIdx.x * 128;

    int aRowG = row0 + tid;
    if (aRowG >= M) aRowG = M - 1;
    const float* Arow = A + (size_t)aRowG * K;

    int brow = tid >> 3, bc = (tid & 7) * 8;

    float acc[8][8] = {};
    float4 rA[4], rB0, rB1;

    {
        rA[0] = *(const float4*)&Arow[0];
        rA[1] = *(const float4*)&Arow[4];
        rA[2] = *(const float4*)&Arow[8];
        rA[3] = *(const float4*)&Arow[12];
        rB0 = *(const float4*)&B[(size_t)brow * N + bc];
        rB1 = *(const float4*)&B[(size_t)brow * N + bc + 4];
#pragma unroll
        for (int q = 0; q < 4; q++) {
            As[0][q * 4 + 0][tid] = ((float*)&rA[q])[0];
            As[0][q * 4 + 1][tid] = ((float*)&rA[q])[1];
            As[0][q * 4 + 2][tid] = ((float*)&rA[q])[2];
            As[0][q * 4 + 3][tid] = ((float*)&rA[q])[3];
        }
        *(float4*)&Bs[0][brow][bc] = rB0;
        *(float4*)&Bs[0][brow][bc + 4] = rB1;
    }
    __syncthreads();

    int buf = 0;
    for (int k0 = 0; k0 < K; k0 += 16, buf ^= 1) {
        bool more = (k0 + 16 < K);
        if (more) {
            rA[0] = *(const float4*)&Arow[k0 + 16];
            rA[1] = *(const float4*)&Arow[k0 + 20];
            rA[2] = *(const float4*)&Arow[k0 + 24];
            rA[3] = *(const float4*)&Arow[k0 + 28];
            rB0 = *(const float4*)&B[(size_t)(k0 + 16 + brow) * N + bc];
            rB1 = *(const float4*)&B[(size_t)(k0 + 16 + brow) * N + bc + 4];
        }
#pragma unroll
        for (int kk = 0; kk < 16; kk++) {
            float a[8], b[8];
            *(float4*)&a[0] = *(float4*)&As[buf][kk][ty * 8];
            *(float4*)&a[4] = *(float4*)&As[buf][kk][ty * 8 + 4];
            *(float4*)&b[0] = *(float4*)&Bs[buf][kk][tx * 8];
            *(float4*)&b[4] = *(float4*)&Bs[buf][kk][tx * 8 + 4];
#pragma unroll
            for (int i = 0; i < 8; i++)
#pragma unroll
                for (int j = 0; j < 8; j++)
                    acc[i][j] += a[i] * b[j];
        }
        if (more) {
            int nb = buf ^ 1;
#pragma unroll
            for (int q = 0; q < 4; q++) {
                As[nb][q * 4 + 0][tid] = ((float*)&rA[q])[0];
                As[nb][q * 4 + 1][tid] = ((float*)&rA[q])[1];
                As[nb][q * 4 + 2][tid] = ((float*)&rA[q])[2];
                As[nb][q * 4 + 3][tid] = ((float*)&rA[q])[3];
            }
            *(float4*)&Bs[nb][brow][bc] = rB0;
            *(float4*)&Bs[nb][brow][bc + 4] = rB1;
        }
        __syncthreads();
    }

    float asv[8], adv[8];
#pragma unroll
    for (int j = 0; j < 8; j++) {
        asv[j] = att_src[tx * 8 + j];
        adv[j] = att_dst[tx * 8 + j];
    }
#pragma unroll
    for (int i = 0; i < 8; i++) {
        int r = row0 + ty * 8 + i;
        if (r < M) {
            // pack 8 fp32 -> 4 bf16x2 -> one 16B store
            __nv_bfloat162 p[4];
#pragma unroll
            for (int q = 0; q < 4; q++)
                p[q] = __float22bfloat162_rn(make_float2(acc[i][q * 2], acc[i][q * 2 + 1]));
            *(uint4*)&g_h1b[r * 32 + tx * 4] = *(uint4*)p;

            float as = 0.f, ad = 0.f;
#pragma unroll
            for (int j = 0; j < 8; j++) {
                as += acc[i][j] * asv[j];
                ad += acc[i][j] * adv[j];
            }
            g_asrc1[r * 8 + tx] = as;
            g_adst1[r * 8 + tx] = ad;
        }
    }
}

// ---------------- CSR build (scalar: max atomic parallelism) ----------------
__global__ void hist_dst(const int* __restrict__ ei, int E) {
    int e = blockIdx.x * blockDim.x + threadIdx.x;
    if (e < E) atomicAdd(&g_deg[ei[E + e]], 1);
}

__global__ void scan_local(int Nn) {
    __shared__ int wsum[32];
    int i = blockIdx.x * 1024 + threadIdx.x;
    int lane = threadIdx.x & 31, wid = threadIdx.x >> 5;
    int v = (i < Nn) ? g_deg[i] : 0;
    int sc = v;
#pragma unroll
    for (int o = 1; o < 32; o <<= 1) {
        int t = __shfl_up_sync(~0u, sc, o);
        if (lane >= o) sc += t;
    }
    if (lane == 31) wsum[wid] = sc;
    __syncthreads();
    if (wid == 0) {
        int ws = wsum[lane];
#pragma unroll
        for (int o = 1; o < 32; o <<= 1) {
            int t = __shfl_up_sync(~0u, ws, o);
            if (lane >= o) ws += t;
        }
        wsum[lane] = ws;
    }
    __syncthreads();
    int excl = sc - v + (wid > 0 ? wsum[wid - 1] : 0);
    if (i < Nn) g_start[i] = excl;
    if (threadIdx.x == 1023) g_bsum[blockIdx.x] = excl + v;
}

__global__ void scan_spine(int nb, int Nn) {
    int lane = threadIdx.x;
    int v0 = (lane * 2 < nb) ? g_bsum[lane * 2] : 0;
    int v1 = (lane * 2 + 1 < nb) ? g_bsum[lane * 2 + 1] : 0;
    int s = v0 + v1;
    int sc = s;
#pragma unroll
    for (int o = 1; o < 32; o <<= 1) {
        int t = __shfl_up_sync(~0u, sc, o);
        if (lane >= o) sc += t;
    }
    int excl = sc - s;
    if (lane * 2 < nb) g_bsum[lane * 2] = excl;
    if (lane * 2 + 1 < nb) g_bsum[lane * 2 + 1] = excl + v0;
    if (lane == 31) g_start[Nn] = sc;
}

__global__ void scan_add(int Nn) {
    int i = blockIdx.x * blockDim.x + threadIdx.x;
    if (i >= Nn) return;
    int s = g_start[i] + g_bsum[i >> 10];
    g_start[i] = s;
    g_cursor[i] = s;
}

__global__ void scatter_csr(const int* __restrict__ ei, int E) {
    int e = blockIdx.x * blockDim.x + threadIdx.x;
    if (e >= E) return;
    int d = ei[E + e];
    int pos = atomicAdd(&g_cursor[d], 1);
    g_csrc[pos] = ei[e];
}

// ---------------- SGEMM2 (64x64x16 tiles) + fused node_attn2 ----------------
__global__ void sgemm2(const float* __restrict__ A, const float* __restrict__ B,
                       float* __restrict__ C,
                       const float* __restrict__ att_src, const float* __restrict__ att_dst,
                       int M, int N, int K) {
    __shared__ float As[16][64];
    __shared__ float Bs[16][64];
    __shared__ float sAs[64], sAd[64];
    int tid = threadIdx.x;
    int tx = tid & 15, ty = tid >> 4;
    int row0 = blockIdx.x * 64;

    if (tid < 64) { sAs[tid] = 0.f; sAd[tid] = 0.f; }

    int arow = tid >> 2, ak = (tid & 3) << 2;
    int brow = tid >> 4, bc = (tid & 15) << 2;

    float acc[4][4] = {};

    for (int k0 = 0; k0 < K; k0 += 16) {
        float4 av = make_float4(0.f, 0.f, 0.f, 0.f);
        if (row0 + arow < M)
            av = *(const float4*)&A[(size_t)(row0 + arow) * K + k0 + ak];
        As[ak + 0][arow] = av.x;
        As[ak + 1][arow] = av.y;
        As[ak + 2][arow] = av.z;
        As[ak + 3][arow] = av.w;

        float4 bv = make_float4(0.f, 0.f, 0.f, 0.f);
        if (bc < N)
            bv = *(const float4*)&B[(size_t)(k0 + brow) * N + bc];
        *(float4*)&Bs[brow][bc] = bv;

        __syncthreads();
#pragma unroll
        for (int kk = 0; kk < 16; kk++) {
            float a0 = As[kk][ty * 4 + 0];
            float a1 = As[kk][ty * 4 + 1];
            float a2 = As[kk][ty * 4 + 2];
            float a3 = As[kk][ty * 4 + 3];
            float4 b = *(float4*)&Bs[kk][tx * 4];
            acc[0][0] += a0 * b.x; acc[0][1] += a0 * b.y; acc[0][2] += a0 * b.z; acc[0][3] += a0 * b.w;
            acc[1][0] += a1 * b.x; acc[1][1] += a1 * b.y; acc[1][2] += a1 * b.z; acc[1][3] += a1 * b.w;
            acc[2][0] += a2 * b.x; acc[2][1] += a2 * b.y; acc[2][2] += a2 * b.z; acc[2][3] += a2 * b.w;
            acc[3][0] += a3 * b.x; acc[3][1] += a3 * b.y; acc[3][2] += a3 * b.z; acc[3][3] += a3 * b.w;
        }
        __syncthreads();
    }

#pragma unroll
    for (int i = 0; i < 4; i++) {
        int r = row0 + ty * 4 + i;
        if (r >= M) continue;
        float pas = 0.f, pad = 0.f;
#pragma unroll
        for (int j = 0; j < 4; j++) {
            int c = tx * 4 + j;
            if (c < N) {
                C[(size_t)r * N + c] = acc[i][j];
                pas += acc[i][j] * att_src[c];
                pad += acc[i][j] * att_dst[c];
            }
        }
        if (tx < 10) {
            atomicAdd(&sAs[ty * 4 + i], pas);
            atomicAdd(&sAd[ty * 4 + i], pad);
        }
    }
    __syncthreads();
    if (tid < 64) {
        int r = row0 + tid;
        if (r < M) {
            g_as2[r] = sAs[tid];
            g_ad2[r] = sAd[tid];
        }
    }
}

// ---------------- Layer 1 aggregation: warp per node, bf16 gather ----------------
__global__ void __launch_bounds__(256) agg1(const float* __restrict__ b1, int Nn) {
    int gw = (blockIdx.x * blockDim.x + threadIdx.x) >> 5;
    if (gw >= Nn) return;
    int i = gw;
    int lane = threadIdx.x & 31;
    int h = lane >> 2;

    float adst_w = g_adst1[i * 8 + (lane & 7)];
    float wself = __expf(leaky(g_asrc1[i * 8 + h] + g_adst1[i * 8 + h]));
    float denom = wself;
    float2 hv0 = __bfloat1622float2(g_h1b[i * 32 + lane]);
    float2 acc = make_float2(wself * hv0.x, wself * hv0.y);

    int st = g_start[i], en = g_start[i + 1];
    for (int e0 = st; e0 < en; e0 += 4) {
        int idx = e0 + (lane >> 3);
        bool valid = idx < en;
        int s = valid ? g_csrc[idx] : 0;
        float w = valid ? __expf(leaky(g_asrc1[s * 8 + (lane & 7)] + adst_w)) : 0.f;
#pragma unroll
        for (int j = 0; j < 4; j++) {
            int sj = __shfl_sync(~0u, s, j * 8);
            float wj = __shfl_sync(~0u, w, j * 8 + h);
            float2 hv = __bfloat1622float2(g_h1b[sj * 32 + lane]);
            acc.x += wj * hv.x;
            acc.y += wj * hv.y;
            denom += wj;
        }
    }
    float inv = 1.f / (denom + 1e-16f);
    float2 bb = ((const float2*)b1)[lane];
    float vx = acc.x * inv + bb.x;
    float vy = acc.y * inv + bb.y;
    ((float2*)g_h2in)[i * 32 + lane] = make_float2(vx > 0.f ? vx : 0.f, vy > 0.f ? vy : 0.f);
}

// ---------------- Layer 2 aggregation: warp per node ----------------
__global__ void __launch_bounds__(256) agg2(const float* __restrict__ b2,
                                            float* __restrict__ out, int Nn) {
    int gw = (blockIdx.x * blockDim.x + threadIdx.x) >> 5;
    if (gw >= Nn) return;
    int i = gw;
    int lane = threadIdx.x & 31;
    int cl = lane < 20 ? lane : 0;
    const float2* h2f2 = (const float2*)g_h2;

    float ad = g_ad2[i];
    float wself = __expf(leaky(g_as2[i] + ad));
    float denom = wself;
    float2 hv0 = h2f2[i * 20 + cl];
    float2 acc = make_float2(wself * hv0.x, wself * hv0.y);

    int st = g_start[i], en = g_start[i + 1];
    for (int e0 = st; e0 < en; e0 += 32) {
        int idx = e0 + lane;
        bool valid = idx < en;
        int s = valid ? g_csrc[idx] : 0;
        float w = valid ? __expf(leaky(g_as2[s] + ad)) : 0.f;
        int nleft = en - e0;
        int cnt = nleft < 32 ? nleft : 32;
#pragma unroll 8
        for (int j = 0; j < cnt; j++) {
            int sj = __shfl_sync(~0u, s, j);
            float wj = __shfl_sync(~0u, w, j);
            float2 hv = h2f2[sj * 20 + cl];
            acc.x += wj * hv.x;
            acc.y += wj * hv.y;
            denom += wj;
        }
    }
    float inv = 1.f / (denom + 1e-16f);
    float2 bb = ((const float2*)b2)[cl];
    float vx = acc.x * inv + bb.x;
    float vy = acc.y * inv + bb.y;

    float mloc = (lane < 20) ? fmaxf(vx, vy) : -1e30f;
#pragma unroll
    for (int o = 16; o > 0; o >>= 1) mloc = fmaxf(mloc, __shfl_xor_sync(~0u, mloc, o));
    float sloc = (lane < 20) ? (__expf(vx - mloc) + __expf(vy - mloc)) : 0.f;
#pragma unroll
    for (int o = 16; o > 0; o >>= 1) sloc += __shfl_xor_sync(~0u, sloc, o);
    float lse = mloc + logf(sloc);
    if (lane < 20)
        ((float2*)out)[i * 20 + lane] = make_float2(vx - lse, vy - lse);
}

// ---------------- launch ----------------
extern "C" void kernel_launch(void* const* d_in, const int* in_sizes, int n_in,
                              void* d_out, int out_size) {
    const float* x   = (const float*)d_in[0];
    const int*   ei  = (const int*)d_in[1];
    const float* W1  = (const float*)d_in[2];
    const float* as1 = (const float*)d_in[3];
    const float* ad1 = (const float*)d_in[4];
    const float* b1  = (const float*)d_in[5];
    const float* W2  = (const float*)d_in[6];
    const float* as2 = (const float*)d_in[7];
    const float* ad2 = (const float*)d_in[8];
    const float* b2  = (const float*)d_in[9];
    float* out = (float*)d_out;

    int Nn = in_sizes[0] / 512;   // 50000
    int E  = in_sizes[1] / 2;     // 1600000

    void *ph2in, *ph2, *pdeg;
    cudaGetSymbolAddress(&ph2in, g_h2in);
    cudaGetSymbolAddress(&ph2, g_h2);
    cudaGetSymbolAddress(&pdeg, g_deg);

    const int T = 256;
    int nChunks = (Nn + 1023) / 1024;
    int aggBlocks = (Nn + 7) / 8;

    // CSR build (shared by both layers)
    cudaMemsetAsync(pdeg, 0, (size_t)Nn * sizeof(int));
    hist_dst<<<(E + T - 1) / T, T>>>(ei, E);
    scan_local<<<nChunks, 1024>>>(Nn);
    scan_spine<<<1, 32>>>(nChunks, Nn);
    scan_add<<<(Nn + T - 1) / T, T>>>(Nn);
    scatter_csr<<<(E + T - 1) / T, T>>>(ei, E);

    // layer 1 (attn logits fused into GEMM epilogue, h1 stored bf16)
    sgemm1k<<<(Nn + 127) / 128, 128>>>(x, W1, as1, ad1, Nn);
    agg1<<<aggBlocks, T>>>(b1, Nn);

    // layer 2 (attn logits fused into GEMM epilogue)
    sgemm2<<<(Nn + 63) / 64, T>>>((const float*)ph2in, W2, (float*)ph2, as2, ad2, Nn, 40, 64);
    agg2<<<aggBlocks, T>>>(b2, out, Nn);
}

// round 9
// speedup vs baseline: 1.0146x; 1.0146x over previous
#include <cuda_runtime.h>
#include <cuda_bf16.h>

#define NMAX 50000
#define EMAX 1700000

// ---------------- scratch ----------------
__device__ float g_h1[NMAX * 64];
__device__ float g_asrc1[NMAX * 8];
__device__ float g_adst1[NMAX * 8];
__device__ float g_h2in[NMAX * 64];
__device__ float g_h2[NMAX * 40];
__device__ float g_as2[NMAX];
__device__ float g_ad2[NMAX];
// CSR
__device__ int g_deg[NMAX];
__device__ int g_start[NMAX + 1];
__device__ int g_cursor[NMAX];
__device__ int g_csrc[EMAX];
__device__ int g_bsum[64];

__device__ __forceinline__ float leaky(float e) { return e >= 0.f ? e : 0.2f * e; }

// ---------------- SGEMM1: C[M,64] = A[M,512] @ B[512,64] + fused attn logits ----------------
__global__ void __launch_bounds__(128) sgemm1k(const float* __restrict__ A,
                                               const float* __restrict__ B,
                                               float* __restrict__ C,
                                               const float* __restrict__ att_src,
                                               const float* __restrict__ att_dst,
                                               int M) {
    const int K = 512, N = 64;
    __shared__ float As[2][16][128];
    __shared__ float Bs[2][16][64];
    int tid = threadIdx.x;
    int tx = tid & 7, ty = tid >> 3;
    int row0 = blockIdx.x * 128;

    int aRowG = row0 + tid;
    if (aRowG >= M) aRowG = M - 1;
    const float* Arow = A + (size_t)aRowG * K;

    int brow = tid >> 3, bc = (tid & 7) * 8;

    float acc[8][8] = {};
    float4 rA[4], rB0, rB1;

    {
        rA[0] = *(const float4*)&Arow[0];
        rA[1] = *(const float4*)&Arow[4];
        rA[2] = *(const float4*)&Arow[8];
        rA[3] = *(const float4*)&Arow[12];
        rB0 = *(const float4*)&B[(size_t)brow * N + bc];
        rB1 = *(const float4*)&B[(size_t)brow * N + bc + 4];
#pragma unroll
        for (int q = 0; q < 4; q++) {
            As[0][q * 4 + 0][tid] = ((float*)&rA[q])[0];
            As[0][q * 4 + 1][tid] = ((float*)&rA[q])[1];
            As[0][q * 4 + 2][tid] = ((float*)&rA[q])[2];
            As[0][q * 4 + 3][tid] = ((float*)&rA[q])[3];
        }
        *(float4*)&Bs[0][brow][bc] = rB0;
        *(float4*)&Bs[0][brow][bc + 4] = rB1;
    }
    __syncthreads();

    int buf = 0;
    for (int k0 = 0; k0 < K; k0 += 16, buf ^= 1) {
        bool more = (k0 + 16 < K);
        if (more) {
            rA[0] = *(const float4*)&Arow[k0 + 16];
            rA[1] = *(const float4*)&Arow[k0 + 20];
            rA[2] = *(const float4*)&Arow[k0 + 24];
            rA[3] = *(const float4*)&Arow[k0 + 28];
            rB0 = *(const float4*)&B[(size_t)(k0 + 16 + brow) * N + bc];
            rB1 = *(const float4*)&B[(size_t)(k0 + 16 + brow) * N + bc + 4];
        }
#pragma unroll
        for (int kk = 0; kk < 16; kk++) {
            float a[8], b[8];
            *(float4*)&a[0] = *(float4*)&As[buf][kk][ty * 8];
            *(float4*)&a[4] = *(float4*)&As[buf][kk][ty * 8 + 4];
            *(float4*)&b[0] = *(float4*)&Bs[buf][kk][tx * 8];
            *(float4*)&b[4] = *(float4*)&Bs[buf][kk][tx * 8 + 4];
#pragma unroll
            for (int i = 0; i < 8; i++)
#pragma unroll
                for (int j = 0; j < 8; j++)
                    acc[i][j] += a[i] * b[j];
        }
        if (more) {
            int nb = buf ^ 1;
#pragma unroll
            for (int q = 0; q < 4; q++) {
                As[nb][q * 4 + 0][tid] = ((float*)&rA[q])[0];
                As[nb][q * 4 + 1][tid] = ((float*)&rA[q])[1];
                As[nb][q * 4 + 2][tid] = ((float*)&rA[q])[2];
                As[nb][q * 4 + 3][tid] = ((float*)&rA[q])[3];
            }
            *(float4*)&Bs[nb][brow][bc] = rB0;
            *(float4*)&Bs[nb][brow][bc + 4] = rB1;
        }
        __syncthreads();
    }

    float asv[8], adv[8];
#pragma unroll
    for (int j = 0; j < 8; j++) {
        asv[j] = att_src[tx * 8 + j];
        adv[j] = att_dst[tx * 8 + j];
    }
#pragma unroll
    for (int i = 0; i < 8; i++) {
        int r = row0 + ty * 8 + i;
        if (r < M) {
            *(float4*)&C[(size_t)r * N + tx * 8] = *(float4*)&acc[i][0];
            *(float4*)&C[(size_t)r * N + tx * 8 + 4] = *(float4*)&acc[i][4];
            float as = 0.f, ad = 0.f;
#pragma unroll
            for (int j = 0; j < 8; j++) {
                as += acc[i][j] * asv[j];
                ad += acc[i][j] * adv[j];
            }
            g_asrc1[r * 8 + tx] = as;
            g_adst1[r * 8 + tx] = ad;
        }
    }
}

// ---------------- CSR build ----------------
__global__ void hist_dst(const int* __restrict__ ei, int E) {
    int e = blockIdx.x * blockDim.x + threadIdx.x;
    if (e < E) atomicAdd(&g_deg[ei[E + e]], 1);
}

__global__ void scan_local(int Nn) {
    __shared__ int wsum[32];
    int i = blockIdx.x * 1024 + threadIdx.x;
    int lane = threadIdx.x & 31, wid = threadIdx.x >> 5;
    int v = (i < Nn) ? g_deg[i] : 0;
    int sc = v;
#pragma unroll
    for (int o = 1; o < 32; o <<= 1) {
        int t = __shfl_up_sync(~0u, sc, o);
        if (lane >= o) sc += t;
    }
    if (lane == 31) wsum[wid] = sc;
    __syncthreads();
    if (wid == 0) {
        int ws = wsum[lane];
#pragma unroll
        for (int o = 1; o < 32; o <<= 1) {
            int t = __shfl_up_sync(~0u, ws, o);
            if (lane >= o) ws += t;
        }
        wsum[lane] = ws;
    }
    __syncthreads();
    int excl = sc - v + (wid > 0 ? wsum[wid - 1] : 0);
    if (i < Nn) g_start[i] = excl;
    if (threadIdx.x == 1023) g_bsum[blockIdx.x] = excl + v;
}

__global__ void scan_spine(int nb, int Nn) {
    int lane = threadIdx.x;
    int v0 = (lane * 2 < nb) ? g_bsum[lane * 2] : 0;
    int v1 = (lane * 2 + 1 < nb) ? g_bsum[lane * 2 + 1] : 0;
    int s = v0 + v1;
    int sc = s;
#pragma unroll
    for (int o = 1; o < 32; o <<= 1) {
        int t = __shfl_up_sync(~0u, sc, o);
        if (lane >= o) sc += t;
    }
    int excl = sc - s;
    if (lane * 2 < nb) g_bsum[lane * 2] = excl;
    if (lane * 2 + 1 < nb) g_bsum[lane * 2 + 1] = excl + v0;
    if (lane == 31) g_start[Nn] = sc;
}

__global__ void scan_add(int Nn) {
    int i = blockIdx.x * blockDim.x + threadIdx.x;
    if (i >= Nn) return;
    int s = g_start[i] + g_bsum[i >> 10];
    g_start[i] = s;
    g_cursor[i] = s;
}

__global__ void scatter_csr(const int* __restrict__ ei, int E) {
    int e = blockIdx.x * blockDim.x + threadIdx.x;
    if (e >= E) return;
    int d = ei[E + e];
    int pos = atomicAdd(&g_cursor[d], 1);
    g_csrc[pos] = ei[e];
}

// ---------------- layer-2 attention logits (separate; fusion regressed) ----------------
__global__ void node_attn2(const float* __restrict__ att_src, const float* __restrict__ att_dst, int Nn) {
    int i = blockIdx.x * blockDim.x + threadIdx.x;
    if (i >= Nn) return;
    const float* h = &g_h2[i * 40];
    float as = 0.f, ad = 0.f;
#pragma unroll
    for (int c = 0; c < 40; c++) {
        float v = h[c];
        as += v * att_src[c];
        ad += v * att_dst[c];
    }
    g_as2[i] = as;
    g_ad2[i] = ad;
}

// ---------------- SGEMM2 (64x64x16 tiles) ----------------
__global__ void sgemm64(const float* __restrict__ A, const float* __restrict__ B,
                        float* __restrict__ C, int M, int N, int K) {
    __shared__ float As[16][64];
    __shared__ float Bs[16][64];
    int tid = threadIdx.x;
    int tx = tid & 15, ty = tid >> 4;
    int row0 = blockIdx.x * 64;

    int arow = tid >> 2, ak = (tid & 3) << 2;
    int brow = tid >> 4, bc = (tid & 15) << 2;

    float acc[4][4] = {};

    for (int k0 = 0; k0 < K; k0 += 16) {
        float4 av = make_float4(0.f, 0.f, 0.f, 0.f);
        if (row0 + arow < M)
            av = *(const float4*)&A[(size_t)(row0 + arow) * K + k0 + ak];
        As[ak + 0][arow] = av.x;
        As[ak + 1][arow] = av.y;
        As[ak + 2][arow] = av.z;
        As[ak + 3][arow] = av.w;

        float4 bv = make_float4(0.f, 0.f, 0.f, 0.f);
        if (bc < N)
            bv = *(const float4*)&B[(size_t)(k0 + brow) * N + bc];
        *(float4*)&Bs[brow][bc] = bv;

        __syncthreads();
#pragma unroll
        for (int kk = 0; kk < 16; kk++) {
            float a0 = As[kk][ty * 4 + 0];
            float a1 = As[kk][ty * 4 + 1];
            float a2 = As[kk][ty * 4 + 2];
            float a3 = As[kk][ty * 4 + 3];
            float4 b = *(float4*)&Bs[kk][tx * 4];
            acc[0][0] += a0 * b.x; acc[0][1] += a0 * b.y; acc[0][2] += a0 * b.z; acc[0][3] += a0 * b.w;
            acc[1][0] += a1 * b.x; acc[1][1] += a1 * b.y; acc[1][2] += a1 * b.z; acc[1][3] += a1 * b.w;
            acc[2][0] += a2 * b.x; acc[2][1] += a2 * b.y; acc[2][2] += a2 * b.z; acc[2][3] += a2 * b.w;
            acc[3][0] += a3 * b.x; acc[3][1] += a3 * b.y; acc[3][2] += a3 * b.z; acc[3][3] += a3 * b.w;
        }
        __syncthreads();
    }
#pragma unroll
    for (int i = 0; i < 4; i++) {
        int r = row0 + ty * 4 + i;
        if (r >= M) continue;
#pragma unroll
        for (int j = 0; j < 4; j++) {
            int c = tx * 4 + j;
            if (c < N) C[(size_t)r * N + c] = acc[i][j];
        }
    }
}

// ---------------- Layer 1 aggregation: warp per node, software-pipelined ----------------
__global__ void __launch_bounds__(256) agg1(const float* __restrict__ b1, int Nn) {
    int gw = (blockIdx.x * blockDim.x + threadIdx.x) >> 5;
    if (gw >= Nn) return;
    int i = gw;
    int lane = threadIdx.x & 31;
    int h = lane >> 2;
    const float2* h1f2 = (const float2*)g_h1;

    float adst_w = g_adst1[i * 8 + (lane & 7)];
    float wself = __expf(leaky(g_asrc1[i * 8 + h] + g_adst1[i * 8 + h]));
    float denom = wself;
    float2 hv0 = h1f2[i * 32 + lane];
    float2 acc = make_float2(wself * hv0.x, wself * hv0.y);

    int st = g_start[i], en = g_start[i + 1];

    // prologue: load chunk 0's src index + weight
    int idx = st + (lane >> 3);
    bool v0 = idx < en;
    int s_cur = v0 ? g_csrc[idx] : 0;
    float w_cur = v0 ? __expf(leaky(g_asrc1[s_cur * 8 + (lane & 7)] + adst_w)) : 0.f;

    for (int e0 = st; e0 < en; e0 += 4) {
        // prefetch next chunk's src index (overlaps with gathers below)
        int idx2 = e0 + 4 + (lane >> 3);
        bool vn = idx2 < en;
        int s_nxt = vn ? g_csrc[idx2] : 0;

        // gathers + FMA for current chunk
#pragma unroll
        for (int j = 0; j < 4; j++) {
            int sj = __shfl_sync(~0u, s_cur, j * 8);
            float wj = __shfl_sync(~0u, w_cur, j * 8 + h);
            float2 hv = h1f2[sj * 32 + lane];
            acc.x += wj * hv.x;
            acc.y += wj * hv.y;
            denom += wj;
        }

        // next chunk's weight (asrc gather overlaps with FMAs above)
        w_cur = vn ? __expf(leaky(g_asrc1[s_nxt * 8 + (lane & 7)] + adst_w)) : 0.f;
        s_cur = s_nxt;
    }
    float inv = 1.f / (denom + 1e-16f);
    float2 bb = ((const float2*)b1)[lane];
    float vx = acc.x * inv + bb.x;
    float vy = acc.y * inv + bb.y;
    ((float2*)g_h2in)[i * 32 + lane] = make_float2(vx > 0.f ? vx : 0.f, vy > 0.f ? vy : 0.f);
}

// ---------------- Layer 2 aggregation: warp per node, software-pipelined ----------------
__global__ void __launch_bounds__(256) agg2(const float* __restrict__ b2,
                                            float* __restrict__ out, int Nn) {
    int gw = (blockIdx.x * blockDim.x + threadIdx.x) >> 5;
    if (gw >= Nn) return;
    int i = gw;
    int lane = threadIdx.x & 31;
    int cl = lane < 20 ? lane : 0;
    const float2* h2f2 = (const float2*)g_h2;

    float ad = g_ad2[i];
    float wself = __expf(leaky(g_as2[i] + ad));
    float denom = wself;
    float2 hv0 = h2f2[i * 20 + cl];
    float2 acc = make_float2(wself * hv0.x, wself * hv0.y);

    int st = g_start[i], en = g_start[i + 1];

    // prologue: load chunk 0 (32 edges)
    int idx = st + lane;
    bool v0 = idx < en;
    int s_cur = v0 ? g_csrc[idx] : 0;
    float w_cur = v0 ? __expf(leaky(g_as2[s_cur] + ad)) : 0.f;

    for (int e0 = st; e0 < en; e0 += 32) {
        int idx2 = e0 + 32 + lane;
        bool vn = idx2 < en;
        int s_nxt = vn ? g_csrc[idx2] : 0;

        int nleft = en - e0;
        int cnt = nleft < 32 ? nleft : 32;
#pragma unroll 8
        for (int j = 0; j < cnt; j++) {
            int sj = __shfl_sync(~0u, s_cur, j);
            float wj = __shfl_sync(~0u, w_cur, j);
            float2 hv = h2f2[sj * 20 + cl];
            acc.x += wj * hv.x;
            acc.y += wj * hv.y;
            denom += wj;
        }

        w_cur = vn ? __expf(leaky(g_as2[s_nxt] + ad)) : 0.f;
        s_cur = s_nxt;
    }
    float inv = 1.f / (denom + 1e-16f);
    float2 bb = ((const float2*)b2)[cl];
    float vx = acc.x * inv + bb.x;
    float vy = acc.y * inv + bb.y;

    float mloc = (lane < 20) ? fmaxf(vx, vy) : -1e30f;
#pragma unroll
    for (int o = 16; o > 0; o >>= 1) mloc = fmaxf(mloc, __shfl_xor_sync(~0u, mloc, o));
    float sloc = (lane < 20) ? (__expf(vx - mloc) + __expf(vy - mloc)) : 0.f;
#pragma unroll
    for (int o = 16; o > 0; o >>= 1) sloc += __shfl_xor_sync(~0u, sloc, o);
    float lse = mloc + logf(sloc);
    if (lane < 20)
        ((float2*)out)[i * 20 + lane] = make_float2(vx - lse, vy - lse);
}

// ---------------- launch ----------------
extern "C" void kernel_launch(void* const* d_in, const int* in_sizes, int n_in,
                              void* d_out, int out_size) {
    const float* x   = (const float*)d_in[0];
    const int*   ei  = (const int*)d_in[1];
    const float* W1  = (const float*)d_in[2];
    const float* as1 = (const float*)d_in[3];
    const float* ad1 = (const float*)d_in[4];
    const float* b1  = (const float*)d_in[5];
    const float* W2  = (const float*)d_in[6];
    const float* as2 = (const float*)d_in[7];
    const float* ad2 = (const float*)d_in[8];
    const float* b2  = (const float*)d_in[9];
    float* out = (float*)d_out;

    int Nn = in_sizes[0] / 512;   // 50000
    int E  = in_sizes[1] / 2;     // 1600000

    void *ph1, *ph2in, *ph2, *pdeg;
    cudaGetSymbolAddress(&ph1, g_h1);
    cudaGetSymbolAddress(&ph2in, g_h2in);
    cudaGetSymbolAddress(&ph2, g_h2);
    cudaGetSymbolAddress(&pdeg, g_deg);

    const int T = 256;
    int nChunks = (Nn + 1023) / 1024;
    int aggBlocks = (Nn + 7) / 8;

    // CSR build (shared by both layers)
    cudaMemsetAsync(pdeg, 0, (size_t)Nn * sizeof(int));
    hist_dst<<<(E + T - 1) / T, T>>>(ei, E);
    scan_local<<<nChunks, 1024>>>(Nn);
    scan_spine<<<1, 32>>>(nChunks, Nn);
    scan_add<<<(Nn + T - 1) / T, T>>>(Nn);
    scatter_csr<<<(E + T - 1) / T, T>>>(ei, E);

    // layer 1 (attn logits fused into GEMM epilogue)
    sgemm1k<<<(Nn + 127) / 128, 128>>>(x, W1, (float*)ph1, as1, ad1, Nn);
    agg1<<<aggBlocks, T>>>(b1, Nn);

    // layer 2
    sgemm64<<<(Nn + 63) / 64, T>>>((const float*)ph2in, W2, (float*)ph2, Nn, 40, 64);
    node_attn2<<<(Nn + T - 1) / T, T>>>(as2, ad2, Nn);
    agg2<<<aggBlocks, T>>>(b2, out, Nn);
}